// round 16
// baseline (speedup 1.0000x reference)
#include <cuda_runtime.h>
#include <cuda_fp16.h>
#include <math.h>
#include <stdint.h>

#define BATCH 8
#define TLEN  4096
#define DDIM  512
#define HDIM  1024
#define MROWS (BATCH*TLEN)   // 32768
#define TH    (TLEN*HDIM)    // 2^22
#define TK    32

typedef __half f16;

// ---------------- scratch (device globals, no allocation) ----------------
__device__ f16   g_x1[MROWS*DDIM];
__device__ f16   g_x3[MROWS*DDIM];
__device__ f16   g_qsig[MROWS*HDIM];
__device__ f16   g_numer[MROWS*HDIM];
__device__ f16   g_v[MROWS*HDIM];
__device__ f16   g_y[MROWS*HDIM];
__device__ f16   g_x2[MROWS*DDIM];
__device__ f16   g_h[MROWS*HDIM];
// transposed fp16 weights: [N,K]
__device__ f16   g_wq[DDIM*HDIM];
__device__ f16   g_wk[DDIM*HDIM];
__device__ f16   g_wv[DDIM*HDIM];
__device__ f16   g_wo[DDIM*HDIM];
__device__ f16   g_w1[DDIM*HDIM];
__device__ f16   g_w2[DDIM*HDIM];

// ================= helpers =================
__device__ __forceinline__ uint32_t smem_u32(const void* p) {
    uint32_t a;
    asm("{ .reg .u64 t; cvta.to.shared.u64 t, %1; cvt.u32.u64 %0, t; }"
        : "=r"(a) : "l"(p));
    return a;
}
__device__ __forceinline__ uint32_t swz64(uint32_t off) {
    return off ^ ((off >> 3) & 0x30);
}
__device__ __forceinline__ void ldsm_x4(uint32_t* r, uint32_t addr) {
    asm volatile("ldmatrix.sync.aligned.m8n8.x4.shared.b16 {%0,%1,%2,%3}, [%4];"
                 : "=r"(r[0]), "=r"(r[1]), "=r"(r[2]), "=r"(r[3]) : "r"(addr));
}
__device__ __forceinline__ void mma_f16(float* d, const uint32_t* a,
                                        uint32_t b0, uint32_t b1) {
    asm volatile("mma.sync.aligned.m16n8k16.row.col.f32.f16.f16.f32 "
                 "{%0,%1,%2,%3}, {%4,%5,%6,%7}, {%8,%9}, {%0,%1,%2,%3};"
                 : "+f"(d[0]), "+f"(d[1]), "+f"(d[2]), "+f"(d[3])
                 : "r"(a[0]), "r"(a[1]), "r"(a[2]), "r"(a[3]), "r"(b0), "r"(b1));
}
__device__ __forceinline__ void cp16(uint32_t dst, const void* src) {
    asm volatile("cp.async.cg.shared.global [%0], [%1], 16;" :: "r"(dst), "l"(src));
}
#define CP_COMMIT() asm volatile("cp.async.commit_group;" ::: "memory")
#define CP_WAIT1()  asm volatile("cp.async.wait_group 1;" ::: "memory")
#define CP_WAIT0()  asm volatile("cp.async.wait_group 0;" ::: "memory")

// ---------------- LayerNorm (f32 input) -> f16 ----------------
__global__ __launch_bounds__(128) void ln_f32_kernel(
    const float* __restrict__ x, const float* __restrict__ gamma,
    const float* __restrict__ beta, f16* __restrict__ out)
{
    const int row = blockIdx.x;
    const int t   = threadIdx.x;
    float4 v = ((const float4*)(x + (size_t)row * DDIM))[t];
    float s  = v.x + v.y + v.z + v.w;
    float ss = v.x*v.x + v.y*v.y + v.z*v.z + v.w*v.w;

    __shared__ float red[2][4];
    const int lane = t & 31, wid = t >> 5;
    #pragma unroll
    for (int o = 16; o > 0; o >>= 1) {
        s  += __shfl_xor_sync(0xffffffffu, s,  o);
        ss += __shfl_xor_sync(0xffffffffu, ss, o);
    }
    if (lane == 0) { red[0][wid] = s; red[1][wid] = ss; }
    __syncthreads();
    s  = red[0][0] + red[0][1] + red[0][2] + red[0][3];
    ss = red[1][0] + red[1][1] + red[1][2] + red[1][3];

    const float mean = s * (1.0f / DDIM);
    const float var  = ss * (1.0f / DDIM) - mean * mean;
    const float rstd = rsqrtf(var + 1e-5f);

    const float4 g4 = ((const float4*)gamma)[t];
    const float4 b4 = ((const float4*)beta)[t];
    f16 o[4];
    o[0] = __float2half_rn((v.x - mean) * rstd * g4.x + b4.x);
    o[1] = __float2half_rn((v.y - mean) * rstd * g4.y + b4.y);
    o[2] = __float2half_rn((v.z - mean) * rstd * g4.z + b4.z);
    o[3] = __float2half_rn((v.w - mean) * rstd * g4.w + b4.w);
    ((uint2*)(out + (size_t)row * DDIM))[t] = *(uint2*)o;
}

// ---------------- LayerNorm (f16 input) -> f16 ----------------
__global__ __launch_bounds__(128) void ln_f16_kernel(
    const f16* __restrict__ x, const float* __restrict__ gamma,
    const float* __restrict__ beta, f16* __restrict__ out)
{
    const int row = blockIdx.x;
    const int t   = threadIdx.x;
    const uint2 raw = ((const uint2*)(x + (size_t)row * DDIM))[t];
    const float2 p0 = __half22float2(*(const __half2*)&raw.x);
    const float2 p1 = __half22float2(*(const __half2*)&raw.y);
    float4 v = make_float4(p0.x, p0.y, p1.x, p1.y);
    float s  = v.x + v.y + v.z + v.w;
    float ss = v.x*v.x + v.y*v.y + v.z*v.z + v.w*v.w;

    __shared__ float red[2][4];
    const int lane = t & 31, wid = t >> 5;
    #pragma unroll
    for (int o = 16; o > 0; o >>= 1) {
        s  += __shfl_xor_sync(0xffffffffu, s,  o);
        ss += __shfl_xor_sync(0xffffffffu, ss, o);
    }
    if (lane == 0) { red[0][wid] = s; red[1][wid] = ss; }
    __syncthreads();
    s  = red[0][0] + red[0][1] + red[0][2] + red[0][3];
    ss = red[1][0] + red[1][1] + red[1][2] + red[1][3];

    const float mean = s * (1.0f / DDIM);
    const float var  = ss * (1.0f / DDIM) - mean * mean;
    const float rstd = rsqrtf(var + 1e-5f);

    const float4 g4 = ((const float4*)gamma)[t];
    const float4 b4 = ((const float4*)beta)[t];
    f16 o[4];
    o[0] = __float2half_rn((v.x - mean) * rstd * g4.x + b4.x);
    o[1] = __float2half_rn((v.y - mean) * rstd * g4.y + b4.y);
    o[2] = __float2half_rn((v.z - mean) * rstd * g4.z + b4.z);
    o[3] = __float2half_rn((v.w - mean) * rstd * g4.w + b4.w);
    ((uint2*)(out + (size_t)row * DDIM))[t] = *(uint2*)o;
}

// ------- fused weight transpose + fp16 round (all 6 weights, one launch) ---
__global__ __launch_bounds__(256) void wsplit6_kernel(
    const float* __restrict__ Wq, const float* __restrict__ Wk,
    const float* __restrict__ Wv, const float* __restrict__ Wo,
    const float* __restrict__ W1, const float* __restrict__ W2,
    f16* __restrict__ oq, f16* __restrict__ ok, f16* __restrict__ ov,
    f16* __restrict__ oo, f16* __restrict__ o1, f16* __restrict__ o2)
{
    const int w = blockIdx.y;
    const float* W;
    f16* Wh;
    int K, N;
    switch (w) {
        case 0: W = Wq; Wh = oq; K = DDIM; N = HDIM; break;
        case 1: W = Wk; Wh = ok; K = DDIM; N = HDIM; break;
        case 2: W = Wv; Wh = ov; K = DDIM; N = HDIM; break;
        case 3: W = Wo; Wh = oo; K = HDIM; N = DDIM; break;
        case 4: W = W1; Wh = o1; K = DDIM; N = HDIM; break;
        default: W = W2; Wh = o2; K = HDIM; N = DDIM; break;
    }
    const int nb = N / 32;
    const int n0 = (blockIdx.x % nb) * 32;
    const int k0 = (blockIdx.x / nb) * 32;

    __shared__ float tbuf[32][33];
    const int tx = threadIdx.x & 31;
    const int ty = threadIdx.x >> 5;
    #pragma unroll
    for (int i = 0; i < 4; ++i)
        tbuf[ty + i * 8][tx] = W[(size_t)(k0 + ty + i * 8) * N + n0 + tx];
    __syncthreads();
    #pragma unroll
    for (int i = 0; i < 4; ++i) {
        const int n = n0 + ty + i * 8;
        Wh[(size_t)n * K + k0 + tx] = __float2half_rn(tbuf[tx][ty + i * 8]);
    }
}

// ------- fused AFT reduction + Y (all f16 traffic, f32 math) ----
__global__ __launch_bounds__(256) void aft_y_kernel(
    const f16* __restrict__ numer, const f16* __restrict__ v,
    const f16* __restrict__ qsig, f16* __restrict__ y)
{
    const size_t i4 = ((size_t)blockIdx.x * blockDim.x + threadIdx.x) * 4;
    float den[4] = {0.f, 0.f, 0.f, 0.f};
    float num[4] = {0.f, 0.f, 0.f, 0.f};
    #pragma unroll
    for (int b = 0; b < BATCH; ++b) {
        const uint2 nr = *(const uint2*)(numer + (size_t)b * TH + i4);
        const uint2 vr = *(const uint2*)(v     + (size_t)b * TH + i4);
        const float2 n0 = __half22float2(*(const __half2*)&nr.x);
        const float2 n1 = __half22float2(*(const __half2*)&nr.y);
        const float2 v0 = __half22float2(*(const __half2*)&vr.x);
        const float2 v1 = __half22float2(*(const __half2*)&vr.y);
        den[0] += n0.x; den[1] += n0.y; den[2] += n1.x; den[3] += n1.y;
        num[0] = fmaf(n0.x, v0.x, num[0]);
        num[1] = fmaf(n0.y, v0.y, num[1]);
        num[2] = fmaf(n1.x, v1.x, num[2]);
        num[3] = fmaf(n1.y, v1.y, num[3]);
    }
    const float w0 = num[0] / den[0], w1 = num[1] / den[1];
    const float w2 = num[2] / den[2], w3 = num[3] / den[3];
    #pragma unroll
    for (int b = 0; b < BATCH; ++b) {
        const size_t idx = (size_t)b * TH + i4;
        const uint2 qr = *(const uint2*)(qsig + idx);
        const float2 q0 = __half22float2(*(const __half2*)&qr.x);
        const float2 q1 = __half22float2(*(const __half2*)&qr.y);
        f16 o[4];
        o[0] = __float2half_rn(q0.x * w0);
        o[1] = __float2half_rn(q0.y * w1);
        o[2] = __float2half_rn(q1.x * w2);
        o[3] = __float2half_rn(q1.y * w3);
        *(uint2*)(y + idx) = *(uint2*)o;
    }
}

// ========== GEMM mainloop: 128 threads, 4 warps of 64x64, TK=32 ==========
// acc += A[bm:128, :K] * B[bn:128, :K]^T
__device__ __forceinline__ void gemm_main(
    const f16* __restrict__ A, const f16* __restrict__ Bm,
    int bm, int bn, int K, uint32_t sb, int tid,
    float (&acc)[4][8][4])
{
    constexpr uint32_t T_B = 8192u;
    constexpr uint32_t STG = 16384u;

    const int wid  = tid >> 5;
    const int lane = tid & 31;
    const int wm = (wid >> 1) * 64;      // warp tile 64x64
    const int wn = (wid & 1) * 64;
    const int rowA = lane & 15;
    const int khA  = lane >> 4;
    const int rowB = (lane & 7) + ((lane >> 4) << 3);
    const int khB  = (lane >> 3) & 1;
    const int lr = tid >> 2;             // 0..31
    const int ls = tid & 3;              // 16B seg 0..3
    const int nchunks = K / TK;

    auto prefetch = [&](int chunk, uint32_t base) {
        const int k0 = chunk * TK;
        #pragma unroll
        for (int h = 0; h < 4; ++h) {
            const int r = lr + h * 32;
            const uint32_t so = swz64((uint32_t)(r * 64 + ls * 16));
            const size_t asrc = (size_t)(bm + r) * K + k0 + ls * 8;
            const size_t bsrc = (size_t)(bn + r) * K + k0 + ls * 8;
            cp16(base + so,       A  + asrc);
            cp16(base + T_B + so, Bm + bsrc);
        }
    };

    prefetch(0, sb);
    CP_COMMIT();
    prefetch(1, sb + STG);
    CP_COMMIT();

    int cst = 0, pst = 2;
    for (int c = 0; c < nchunks; ++c) {
        if (c < nchunks - 1) CP_WAIT1(); else CP_WAIT0();
        __syncthreads();

        if (c + 2 < nchunks) {
            prefetch(c + 2, sb + pst * STG);
            CP_COMMIT();
            pst = (pst + 1 == 3) ? 0 : pst + 1;
        }

        const uint32_t buf = sb + cst * STG;
        cst = (cst + 1 == 3) ? 0 : cst + 1;

        #pragma unroll
        for (int s = 0; s < 2; ++s) {
            uint32_t ah[4][4], bh[4][4];
            #pragma unroll
            for (int mi = 0; mi < 4; ++mi) {
                const uint32_t off = (uint32_t)((wm + mi * 16 + rowA) * 64
                                                + s * 32 + khA * 16);
                ldsm_x4(ah[mi], buf + swz64(off));
            }
            #pragma unroll
            for (int nj = 0; nj < 4; ++nj) {
                const uint32_t off = (uint32_t)((wn + nj * 16 + rowB) * 64
                                                + s * 32 + khB * 16);
                ldsm_x4(bh[nj], buf + T_B + swz64(off));
            }
            #pragma unroll
            for (int mi = 0; mi < 4; ++mi)
                #pragma unroll
                for (int ni = 0; ni < 8; ++ni) {
                    const uint32_t* bb = bh[ni >> 1];
                    mma_f16(acc[mi][ni], ah[mi], bb[(ni & 1) * 2], bb[(ni & 1) * 2 + 1]);
                }
        }
    }
}

#define SMEM_BYTES 49152   // 3 stages * 16KB

// ---------------- fused QKV GEMM (f16 outputs) ----------------
__global__ __launch_bounds__(128, 2) void tc_gemm_qkv(
    const f16* __restrict__ A,
    const f16* __restrict__ Bq, const f16* __restrict__ Bk,
    const f16* __restrict__ Bv,
    const float* __restrict__ bq, const float* __restrict__ bk,
    const float* __restrict__ bv, const float* __restrict__ wbias,
    f16* __restrict__ Cq, f16* __restrict__ Ck, f16* __restrict__ Cv)
{
    extern __shared__ char smem[];
    const uint32_t sb = smem_u32(smem);
    const int tid = threadIdx.x;
    const int which = blockIdx.x >> 3;          // 0=Q 1=K 2=V
    const int bn = (blockIdx.x & 7) * 128;
    const int bm = blockIdx.y * 128;

    const f16* B = (which == 0) ? Bq : (which == 1) ? Bk : Bv;
    const float* bias = (which == 0) ? bq : (which == 1) ? bk : bv;
    f16* C = (which == 0) ? Cq : (which == 1) ? Ck : Cv;

    float acc[4][8][4];
    #pragma unroll
    for (int mi = 0; mi < 4; ++mi)
        #pragma unroll
        for (int ni = 0; ni < 8; ++ni)
            #pragma unroll
            for (int r = 0; r < 4; ++r) acc[mi][ni][r] = 0.f;

    gemm_main(A, B, bm, bn, DDIM, sb, tid, acc);

    const int wid = tid >> 5, lane = tid & 31;
    const int wm = (wid >> 1) * 64, wn = (wid & 1) * 64;
    const int qid = lane >> 2, tc = (lane & 3) * 2;
    #pragma unroll
    for (int mi = 0; mi < 4; ++mi)
        #pragma unroll
        for (int half = 0; half < 2; ++half) {
            const int m = bm + wm + mi * 16 + qid + half * 8;
            #pragma unroll
            for (int ni = 0; ni < 8; ++ni) {
                const int n = bn + wn + ni * 8 + tc;
                float v0 = acc[mi][ni][half * 2 + 0] + bias[n];
                float v1 = acc[mi][ni][half * 2 + 1] + bias[n + 1];
                if (which == 0) {
                    v0 = 1.0f / (1.0f + expf(-v0));
                    v1 = 1.0f / (1.0f + expf(-v1));
                } else if (which == 1) {
                    v0 = expf(v0 + wbias[n]);
                    v1 = expf(v1 + wbias[n + 1]);
                }
                const __half2 o = __floats2half2_rn(v0, v1);
                *(__half2*)(C + (size_t)m * HDIM + n) = o;
            }
        }
}

// ---------------- generic GEMM ----------------
// EPI: 3 +bias+resid(f16) -> f16 | 4 gelu -> f16 | 5 2*(+bias) -> f32
template<int EPI>
__global__ __launch_bounds__(128, 2) void tc_gemm(
    const f16* __restrict__ A, const f16* __restrict__ Bm,
    const float* __restrict__ bias, const f16* __restrict__ resid,
    float* __restrict__ Cf, f16* __restrict__ Ch,
    int N, int K)
{
    extern __shared__ char smem[];
    const uint32_t sb = smem_u32(smem);
    const int tid = threadIdx.x;
    const int bm = blockIdx.y * 128;
    const int bn = blockIdx.x * 128;

    float acc[4][8][4];
    #pragma unroll
    for (int mi = 0; mi < 4; ++mi)
        #pragma unroll
        for (int ni = 0; ni < 8; ++ni)
            #pragma unroll
            for (int r = 0; r < 4; ++r) acc[mi][ni][r] = 0.f;

    gemm_main(A, Bm, bm, bn, K, sb, tid, acc);

    const int wid = tid >> 5, lane = tid & 31;
    const int wm = (wid >> 1) * 64, wn = (wid & 1) * 64;
    const int qid = lane >> 2, tc = (lane & 3) * 2;
    #pragma unroll
    for (int mi = 0; mi < 4; ++mi)
        #pragma unroll
        for (int half = 0; half < 2; ++half) {
            const int m = bm + wm + mi * 16 + qid + half * 8;
            const f16* rr = (EPI == 3) ? (resid + (size_t)m * N) : nullptr;
            #pragma unroll
            for (int ni = 0; ni < 8; ++ni) {
                const int n = bn + wn + ni * 8 + tc;
                float v0 = acc[mi][ni][half * 2 + 0] + bias[n];
                float v1 = acc[mi][ni][half * 2 + 1] + bias[n + 1];
                if (EPI == 3) {
                    const float2 rf = __half22float2(*(const __half2*)(rr + n));
                    v0 += rf.x;
                    v1 += rf.y;
                } else if (EPI == 4) {
                    v0 = 0.5f * v0 * (1.0f + erff(v0 * 0.70710678118654752f));
                    v1 = 0.5f * v1 * (1.0f + erff(v1 * 0.70710678118654752f));
                } else if (EPI == 5) {
                    v0 *= 2.0f;
                    v1 *= 2.0f;
                }
                if (EPI == 5) {
                    float2 o; o.x = v0; o.y = v1;
                    *(float2*)(Cf + (size_t)m * N + n) = o;
                } else {
                    const __half2 o = __floats2half2_rn(v0, v1);
                    *(__half2*)(Ch + (size_t)m * N + n) = o;
                }
            }
        }
}

// ---------------- launch ----------------
extern "C" void kernel_launch(void* const* d_in, const int* in_sizes, int n_in,
                              void* d_out, int out_size)
{
    const float* x     = (const float*)d_in[0];
    const float* gamma = (const float*)d_in[1];
    const float* beta  = (const float*)d_in[2];
    const float* Wq    = (const float*)d_in[3];
    const float* bq    = (const float*)d_in[4];
    const float* Wk    = (const float*)d_in[5];
    const float* bk    = (const float*)d_in[6];
    const float* Wv    = (const float*)d_in[7];
    const float* bv    = (const float*)d_in[8];
    const float* wbias = (const float*)d_in[9];
    const float* Wo    = (const float*)d_in[10];
    const float* bo    = (const float*)d_in[11];
    const float* W1    = (const float*)d_in[12];
    const float* b1    = (const float*)d_in[13];
    const float* W2    = (const float*)d_in[14];
    const float* b2    = (const float*)d_in[15];
    float* out = (float*)d_out;

    f16 *x1, *x3, *qsig, *numer, *vmat, *y, *x2, *h;
    f16 *wq, *wk, *wv, *wo, *w1, *w2;
    cudaGetSymbolAddress((void**)&x1,    g_x1);
    cudaGetSymbolAddress((void**)&x3,    g_x3);
    cudaGetSymbolAddress((void**)&qsig,  g_qsig);
    cudaGetSymbolAddress((void**)&numer, g_numer);
    cudaGetSymbolAddress((void**)&vmat,  g_v);
    cudaGetSymbolAddress((void**)&y,     g_y);
    cudaGetSymbolAddress((void**)&x2,    g_x2);
    cudaGetSymbolAddress((void**)&h,     g_h);
    cudaGetSymbolAddress((void**)&wq, g_wq);
    cudaGetSymbolAddress((void**)&wk, g_wk);
    cudaGetSymbolAddress((void**)&wv, g_wv);
    cudaGetSymbolAddress((void**)&wo, g_wo);
    cudaGetSymbolAddress((void**)&w1, g_w1);
    cudaGetSymbolAddress((void**)&w2, g_w2);

    cudaFuncSetAttribute(tc_gemm_qkv,
        cudaFuncAttributeMaxDynamicSharedMemorySize, SMEM_BYTES);
    cudaFuncSetAttribute(tc_gemm<3>,
        cudaFuncAttributeMaxDynamicSharedMemorySize, SMEM_BYTES);
    cudaFuncSetAttribute(tc_gemm<4>,
        cudaFuncAttributeMaxDynamicSharedMemorySize, SMEM_BYTES);
    cudaFuncSetAttribute(tc_gemm<5>,
        cudaFuncAttributeMaxDynamicSharedMemorySize, SMEM_BYTES);

    // 0) fused weight transpose + fp16 round (one launch)
    wsplit6_kernel<<<dim3(512, 6), 256>>>(Wq, Wk, Wv, Wo, W1, W2,
        wq, wk, wv, wo, w1, w2);

    // 1) x1 = LN(x) -> f16
    ln_f32_kernel<<<MROWS, 128>>>(x, gamma, beta, x1);

    // 2) fused Q/K/V GEMM -> f16 outputs
    dim3 gQKV(3 * (HDIM / 128), MROWS / 128);
    tc_gemm_qkv<<<gQKV, 128, SMEM_BYTES>>>(x1,
        wq, wk, wv, bq, bk, bv, wbias, qsig, numer, vmat);

    // 3) fused reduce + Y
    aft_y_kernel<<<TH / 1024, 256>>>(numer, vmat, qsig, y);

    // 4) x2 = Y @ Wo + bo + x1 -> f16
    dim3 gO(DDIM / 128, MROWS / 128);
    tc_gemm<3><<<gO, 128, SMEM_BYTES>>>(y, wo, bo, x1, nullptr, x2, DDIM, HDIM);

    // 5) x3 = LN(x2) -> f16
    ln_f16_kernel<<<MROWS, 128>>>(x2, gamma, beta, x3);

    // 6) h = gelu(x3 @ W1 + b1) -> f16
    dim3 gH(HDIM / 128, MROWS / 128);
    tc_gemm<4><<<gH, 128, SMEM_BYTES>>>(x3, w1, b1, nullptr, nullptr, h, HDIM, DDIM);

    // 7) out = 2*(h @ W2 + b2) -> f32
    tc_gemm<5><<<gO, 128, SMEM_BYTES>>>(h, w2, b2, nullptr, out, nullptr, DDIM, HDIM);
}

// round 17
// speedup vs baseline: 1.1563x; 1.1563x over previous
#include <cuda_runtime.h>
#include <cuda_fp16.h>
#include <math.h>
#include <stdint.h>

#define BATCH 8
#define TLEN  4096
#define DDIM  512
#define HDIM  1024
#define MROWS (BATCH*TLEN)   // 32768
#define TH    (TLEN*HDIM)    // 2^22
#define TK    64

typedef __half f16;

// ---------------- scratch (device globals, no allocation) ----------------
__device__ f16   g_x1[MROWS*DDIM];
__device__ f16   g_x3[MROWS*DDIM];
__device__ f16   g_qsig[MROWS*HDIM];
__device__ f16   g_numer[MROWS*HDIM];
__device__ f16   g_v[MROWS*HDIM];
__device__ f16   g_y[MROWS*HDIM];
__device__ f16   g_x2[MROWS*DDIM];
__device__ f16   g_h[MROWS*HDIM];
// transposed fp16 weights: [N,K]
__device__ f16   g_wq[DDIM*HDIM];
__device__ f16   g_wk[DDIM*HDIM];
__device__ f16   g_wv[DDIM*HDIM];
__device__ f16   g_wo[DDIM*HDIM];
__device__ f16   g_w1[DDIM*HDIM];
__device__ f16   g_w2[DDIM*HDIM];

// ================= helpers =================
__device__ __forceinline__ uint32_t smem_u32(const void* p) {
    uint32_t a;
    asm("{ .reg .u64 t; cvta.to.shared.u64 t, %1; cvt.u32.u64 %0, t; }"
        : "=r"(a) : "l"(p));
    return a;
}
// SW128 swizzle for 128B rows
__device__ __forceinline__ uint32_t swz128(uint32_t off) {
    return off ^ ((off >> 3) & 0x70);
}
__device__ __forceinline__ void ldsm_x4(uint32_t* r, uint32_t addr) {
    asm volatile("ldmatrix.sync.aligned.m8n8.x4.shared.b16 {%0,%1,%2,%3}, [%4];"
                 : "=r"(r[0]), "=r"(r[1]), "=r"(r[2]), "=r"(r[3]) : "r"(addr));
}
__device__ __forceinline__ void mma_f16(float* d, const uint32_t* a,
                                        uint32_t b0, uint32_t b1) {
    asm volatile("mma.sync.aligned.m16n8k16.row.col.f32.f16.f16.f32 "
                 "{%0,%1,%2,%3}, {%4,%5,%6,%7}, {%8,%9}, {%0,%1,%2,%3};"
                 : "+f"(d[0]), "+f"(d[1]), "+f"(d[2]), "+f"(d[3])
                 : "r"(a[0]), "r"(a[1]), "r"(a[2]), "r"(a[3]), "r"(b0), "r"(b1));
}
__device__ __forceinline__ void cp16(uint32_t dst, const void* src) {
    asm volatile("cp.async.cg.shared.global [%0], [%1], 16;" :: "r"(dst), "l"(src));
}
#define CP_COMMIT() asm volatile("cp.async.commit_group;" ::: "memory")
#define CP_WAIT1()  asm volatile("cp.async.wait_group 1;" ::: "memory")
#define CP_WAIT0()  asm volatile("cp.async.wait_group 0;" ::: "memory")

// ---------------- LayerNorm (f32 input) -> f16 ----------------
__global__ __launch_bounds__(128) void ln_f32_kernel(
    const float* __restrict__ x, const float* __restrict__ gamma,
    const float* __restrict__ beta, f16* __restrict__ out)
{
    const int row = blockIdx.x;
    const int t   = threadIdx.x;
    float4 v = ((const float4*)(x + (size_t)row * DDIM))[t];
    float s  = v.x + v.y + v.z + v.w;
    float ss = v.x*v.x + v.y*v.y + v.z*v.z + v.w*v.w;

    __shared__ float red[2][4];
    const int lane = t & 31, wid = t >> 5;
    #pragma unroll
    for (int o = 16; o > 0; o >>= 1) {
        s  += __shfl_xor_sync(0xffffffffu, s,  o);
        ss += __shfl_xor_sync(0xffffffffu, ss, o);
    }
    if (lane == 0) { red[0][wid] = s; red[1][wid] = ss; }
    __syncthreads();
    s  = red[0][0] + red[0][1] + red[0][2] + red[0][3];
    ss = red[1][0] + red[1][1] + red[1][2] + red[1][3];

    const float mean = s * (1.0f / DDIM);
    const float var  = ss * (1.0f / DDIM) - mean * mean;
    const float rstd = rsqrtf(var + 1e-5f);

    const float4 g4 = ((const float4*)gamma)[t];
    const float4 b4 = ((const float4*)beta)[t];
    f16 o[4];
    o[0] = __float2half_rn((v.x - mean) * rstd * g4.x + b4.x);
    o[1] = __float2half_rn((v.y - mean) * rstd * g4.y + b4.y);
    o[2] = __float2half_rn((v.z - mean) * rstd * g4.z + b4.z);
    o[3] = __float2half_rn((v.w - mean) * rstd * g4.w + b4.w);
    ((uint2*)(out + (size_t)row * DDIM))[t] = *(uint2*)o;
}

// ---------------- LayerNorm (f16 input) -> f16 ----------------
__global__ __launch_bounds__(128) void ln_f16_kernel(
    const f16* __restrict__ x, const float* __restrict__ gamma,
    const float* __restrict__ beta, f16* __restrict__ out)
{
    const int row = blockIdx.x;
    const int t   = threadIdx.x;
    const uint2 raw = ((const uint2*)(x + (size_t)row * DDIM))[t];
    const float2 p0 = __half22float2(*(const __half2*)&raw.x);
    const float2 p1 = __half22float2(*(const __half2*)&raw.y);
    float4 v = make_float4(p0.x, p0.y, p1.x, p1.y);
    float s  = v.x + v.y + v.z + v.w;
    float ss = v.x*v.x + v.y*v.y + v.z*v.z + v.w*v.w;

    __shared__ float red[2][4];
    const int lane = t & 31, wid = t >> 5;
    #pragma unroll
    for (int o = 16; o > 0; o >>= 1) {
        s  += __shfl_xor_sync(0xffffffffu, s,  o);
        ss += __shfl_xor_sync(0xffffffffu, ss, o);
    }
    if (lane == 0) { red[0][wid] = s; red[1][wid] = ss; }
    __syncthreads();
    s  = red[0][0] + red[0][1] + red[0][2] + red[0][3];
    ss = red[1][0] + red[1][1] + red[1][2] + red[1][3];

    const float mean = s * (1.0f / DDIM);
    const float var  = ss * (1.0f / DDIM) - mean * mean;
    const float rstd = rsqrtf(var + 1e-5f);

    const float4 g4 = ((const float4*)gamma)[t];
    const float4 b4 = ((const float4*)beta)[t];
    f16 o[4];
    o[0] = __float2half_rn((v.x - mean) * rstd * g4.x + b4.x);
    o[1] = __float2half_rn((v.y - mean) * rstd * g4.y + b4.y);
    o[2] = __float2half_rn((v.z - mean) * rstd * g4.z + b4.z);
    o[3] = __float2half_rn((v.w - mean) * rstd * g4.w + b4.w);
    ((uint2*)(out + (size_t)row * DDIM))[t] = *(uint2*)o;
}

// ------- fused weight transpose + fp16 round (all 6 weights, one launch) ---
__global__ __launch_bounds__(256) void wsplit6_kernel(
    const float* __restrict__ Wq, const float* __restrict__ Wk,
    const float* __restrict__ Wv, const float* __restrict__ Wo,
    const float* __restrict__ W1, const float* __restrict__ W2,
    f16* __restrict__ oq, f16* __restrict__ ok, f16* __restrict__ ov,
    f16* __restrict__ oo, f16* __restrict__ o1, f16* __restrict__ o2)
{
    const int w = blockIdx.y;
    const float* W;
    f16* Wh;
    int K, N;
    switch (w) {
        case 0: W = Wq; Wh = oq; K = DDIM; N = HDIM; break;
        case 1: W = Wk; Wh = ok; K = DDIM; N = HDIM; break;
        case 2: W = Wv; Wh = ov; K = DDIM; N = HDIM; break;
        case 3: W = Wo; Wh = oo; K = HDIM; N = DDIM; break;
        case 4: W = W1; Wh = o1; K = DDIM; N = HDIM; break;
        default: W = W2; Wh = o2; K = HDIM; N = DDIM; break;
    }
    const int nb = N / 32;
    const int n0 = (blockIdx.x % nb) * 32;
    const int k0 = (blockIdx.x / nb) * 32;

    __shared__ float tbuf[32][33];
    const int tx = threadIdx.x & 31;
    const int ty = threadIdx.x >> 5;
    #pragma unroll
    for (int i = 0; i < 4; ++i)
        tbuf[ty + i * 8][tx] = W[(size_t)(k0 + ty + i * 8) * N + n0 + tx];
    __syncthreads();
    #pragma unroll
    for (int i = 0; i < 4; ++i) {
        const int n = n0 + ty + i * 8;
        Wh[(size_t)n * K + k0 + tx] = __float2half_rn(tbuf[tx][ty + i * 8]);
    }
}

// ------- fused AFT reduction + Y (all f16 traffic, f32 math) ----
__global__ __launch_bounds__(256) void aft_y_kernel(
    const f16* __restrict__ numer, const f16* __restrict__ v,
    const f16* __restrict__ qsig, f16* __restrict__ y)
{
    const size_t i4 = ((size_t)blockIdx.x * blockDim.x + threadIdx.x) * 4;
    float den[4] = {0.f, 0.f, 0.f, 0.f};
    float num[4] = {0.f, 0.f, 0.f, 0.f};
    #pragma unroll
    for (int b = 0; b < BATCH; ++b) {
        const uint2 nr = *(const uint2*)(numer + (size_t)b * TH + i4);
        const uint2 vr = *(const uint2*)(v     + (size_t)b * TH + i4);
        const float2 n0 = __half22float2(*(const __half2*)&nr.x);
        const float2 n1 = __half22float2(*(const __half2*)&nr.y);
        const float2 v0 = __half22float2(*(const __half2*)&vr.x);
        const float2 v1 = __half22float2(*(const __half2*)&vr.y);
        den[0] += n0.x; den[1] += n0.y; den[2] += n1.x; den[3] += n1.y;
        num[0] = fmaf(n0.x, v0.x, num[0]);
        num[1] = fmaf(n0.y, v0.y, num[1]);
        num[2] = fmaf(n1.x, v1.x, num[2]);
        num[3] = fmaf(n1.y, v1.y, num[3]);
    }
    const float w0 = num[0] / den[0], w1 = num[1] / den[1];
    const float w2 = num[2] / den[2], w3 = num[3] / den[3];
    #pragma unroll
    for (int b = 0; b < BATCH; ++b) {
        const size_t idx = (size_t)b * TH + i4;
        const uint2 qr = *(const uint2*)(qsig + idx);
        const float2 q0 = __half22float2(*(const __half2*)&qr.x);
        const float2 q1 = __half22float2(*(const __half2*)&qr.y);
        f16 o[4];
        o[0] = __float2half_rn(q0.x * w0);
        o[1] = __float2half_rn(q0.y * w1);
        o[2] = __float2half_rn(q1.x * w2);
        o[3] = __float2half_rn(q1.y * w3);
        *(uint2*)(y + idx) = *(uint2*)o;
    }
}

// ========== GEMM mainloop: 256 threads, 8 warps of 64x32, TK=64 ==========
// acc += A[bm:128, :K] * B[bn:128, :K]^T   (A,B tiles: 128 rows x 128B, SW128)
__device__ __forceinline__ void gemm_main(
    const f16* __restrict__ A, const f16* __restrict__ Bm,
    int bm, int bn, int K, uint32_t sb, int tid,
    float (&acc)[4][4][4])
{
    constexpr uint32_t T_B = 16384u;
    constexpr uint32_t STG = 32768u;

    const int wid  = tid >> 5;
    const int lane = tid & 31;
    const int wm = (wid >> 2) * 64;      // warp tile 64x32
    const int wn = (wid & 3) * 32;
    const int rowA = lane & 15;
    const int khA  = lane >> 4;
    const int rowB = (lane & 7) + ((lane >> 4) << 3);
    const int khB  = (lane >> 3) & 1;
    const int nchunks = K / TK;

    auto prefetch = [&](int chunk, uint32_t base) {
        const int k0 = chunk * TK;
        #pragma unroll
        for (int it = 0; it < 4; ++it) {
            const int idx = tid + it * 256;      // 0..1023
            const int r  = idx >> 3;             // row 0..127
            const int sc = idx & 7;              // 16B seg 0..7
            const uint32_t so = swz128((uint32_t)(r * 128 + sc * 16));
            const size_t asrc = (size_t)(bm + r) * K + k0 + sc * 8;
            const size_t bsrc = (size_t)(bn + r) * K + k0 + sc * 8;
            cp16(base + so,       A  + asrc);
            cp16(base + T_B + so, Bm + bsrc);
        }
    };

    prefetch(0, sb);
    CP_COMMIT();
    prefetch(1, sb + STG);
    CP_COMMIT();

    int cst = 0, pst = 2;
    for (int c = 0; c < nchunks; ++c) {
        if (c < nchunks - 1) CP_WAIT1(); else CP_WAIT0();
        __syncthreads();

        if (c + 2 < nchunks) {
            prefetch(c + 2, sb + pst * STG);
            CP_COMMIT();
            pst = (pst + 1 == 3) ? 0 : pst + 1;
        }

        const uint32_t buf = sb + cst * STG;
        cst = (cst + 1 == 3) ? 0 : cst + 1;

        #pragma unroll
        for (int s = 0; s < 4; ++s) {
            uint32_t ah[4][4], bh[2][4];
            #pragma unroll
            for (int mi = 0; mi < 4; ++mi) {
                const uint32_t off = (uint32_t)((wm + mi * 16 + rowA) * 128
                                                + s * 32 + khA * 16);
                ldsm_x4(ah[mi], buf + swz128(off));
            }
            #pragma unroll
            for (int nj = 0; nj < 2; ++nj) {
                const uint32_t off = (uint32_t)((wn + nj * 16 + rowB) * 128
                                                + s * 32 + khB * 16);
                ldsm_x4(bh[nj], buf + T_B + swz128(off));
            }
            #pragma unroll
            for (int mi = 0; mi < 4; ++mi)
                #pragma unroll
                for (int ni = 0; ni < 4; ++ni) {
                    const uint32_t* bb = bh[ni >> 1];
                    mma_f16(acc[mi][ni], ah[mi], bb[(ni & 1) * 2], bb[(ni & 1) * 2 + 1]);
                }
        }
    }
}

#define SMEM_BYTES 98304   // 3 stages * 32KB

// ---------------- fused QKV GEMM (f16 outputs) ----------------
__global__ __launch_bounds__(256, 2) void tc_gemm_qkv(
    const f16* __restrict__ A,
    const f16* __restrict__ Bq, const f16* __restrict__ Bk,
    const f16* __restrict__ Bv,
    const float* __restrict__ bq, const float* __restrict__ bk,
    const float* __restrict__ bv, const float* __restrict__ wbias,
    f16* __restrict__ Cq, f16* __restrict__ Ck, f16* __restrict__ Cv)
{
    extern __shared__ char smem[];
    const uint32_t sb = smem_u32(smem);
    const int tid = threadIdx.x;
    const int which = blockIdx.x >> 3;          // 0=Q 1=K 2=V
    const int bn = (blockIdx.x & 7) * 128;
    const int bm = blockIdx.y * 128;

    const f16* B = (which == 0) ? Bq : (which == 1) ? Bk : Bv;
    const float* bias = (which == 0) ? bq : (which == 1) ? bk : bv;
    f16* C = (which == 0) ? Cq : (which == 1) ? Ck : Cv;

    float acc[4][4][4];
    #pragma unroll
    for (int mi = 0; mi < 4; ++mi)
        #pragma unroll
        for (int ni = 0; ni < 4; ++ni)
            #pragma unroll
            for (int r = 0; r < 4; ++r) acc[mi][ni][r] = 0.f;

    gemm_main(A, B, bm, bn, DDIM, sb, tid, acc);

    const int wid = tid >> 5, lane = tid & 31;
    const int wm = (wid >> 2) * 64, wn = (wid & 3) * 32;
    const int qid = lane >> 2, tc = (lane & 3) * 2;
    #pragma unroll
    for (int mi = 0; mi < 4; ++mi)
        #pragma unroll
        for (int half = 0; half < 2; ++half) {
            const int m = bm + wm + mi * 16 + qid + half * 8;
            #pragma unroll
            for (int ni = 0; ni < 4; ++ni) {
                const int n = bn + wn + ni * 8 + tc;
                float v0 = acc[mi][ni][half * 2 + 0] + bias[n];
                float v1 = acc[mi][ni][half * 2 + 1] + bias[n + 1];
                if (which == 0) {
                    v0 = 1.0f / (1.0f + expf(-v0));
                    v1 = 1.0f / (1.0f + expf(-v1));
                } else if (which == 1) {
                    v0 = expf(v0 + wbias[n]);
                    v1 = expf(v1 + wbias[n + 1]);
                }
                const __half2 o = __floats2half2_rn(v0, v1);
                *(__half2*)(C + (size_t)m * HDIM + n) = o;
            }
        }
}

// ---------------- generic GEMM ----------------
// EPI: 3 +bias+resid(f16) -> f16 | 4 gelu -> f16 | 5 2*(+bias) -> f32
template<int EPI>
__global__ __launch_bounds__(256, 2) void tc_gemm(
    const f16* __restrict__ A, const f16* __restrict__ Bm,
    const float* __restrict__ bias, const f16* __restrict__ resid,
    float* __restrict__ Cf, f16* __restrict__ Ch,
    int N, int K)
{
    extern __shared__ char smem[];
    const uint32_t sb = smem_u32(smem);
    const int tid = threadIdx.x;
    const int bm = blockIdx.y * 128;
    const int bn = blockIdx.x * 128;

    float acc[4][4][4];
    #pragma unroll
    for (int mi = 0; mi < 4; ++mi)
        #pragma unroll
        for (int ni = 0; ni < 4; ++ni)
            #pragma unroll
            for (int r = 0; r < 4; ++r) acc[mi][ni][r] = 0.f;

    gemm_main(A, Bm, bm, bn, K, sb, tid, acc);

    const int wid = tid >> 5, lane = tid & 31;
    const int wm = (wid >> 2) * 64, wn = (wid & 3) * 32;
    const int qid = lane >> 2, tc = (lane & 3) * 2;
    #pragma unroll
    for (int mi = 0; mi < 4; ++mi)
        #pragma unroll
        for (int half = 0; half < 2; ++half) {
            const int m = bm + wm + mi * 16 + qid + half * 8;
            const f16* rr = (EPI == 3) ? (resid + (size_t)m * N) : nullptr;
            #pragma unroll
            for (int ni = 0; ni < 4; ++ni) {
                const int n = bn + wn + ni * 8 + tc;
                float v0 = acc[mi][ni][half * 2 + 0] + bias[n];
                float v1 = acc[mi][ni][half * 2 + 1] + bias[n + 1];
                if (EPI == 3) {
                    const float2 rf = __half22float2(*(const __half2*)(rr + n));
                    v0 += rf.x;
                    v1 += rf.y;
                } else if (EPI == 4) {
                    v0 = 0.5f * v0 * (1.0f + erff(v0 * 0.70710678118654752f));
                    v1 = 0.5f * v1 * (1.0f + erff(v1 * 0.70710678118654752f));
                } else if (EPI == 5) {
                    v0 *= 2.0f;
                    v1 *= 2.0f;
                }
                if (EPI == 5) {
                    float2 o; o.x = v0; o.y = v1;
                    *(float2*)(Cf + (size_t)m * N + n) = o;
                } else {
                    const __half2 o = __floats2half2_rn(v0, v1);
                    *(__half2*)(Ch + (size_t)m * N + n) = o;
                }
            }
        }
}

// ---------------- launch ----------------
extern "C" void kernel_launch(void* const* d_in, const int* in_sizes, int n_in,
                              void* d_out, int out_size)
{
    const float* x     = (const float*)d_in[0];
    const float* gamma = (const float*)d_in[1];
    const float* beta  = (const float*)d_in[2];
    const float* Wq    = (const float*)d_in[3];
    const float* bq    = (const float*)d_in[4];
    const float* Wk    = (const float*)d_in[5];
    const float* bk    = (const float*)d_in[6];
    const float* Wv    = (const float*)d_in[7];
    const float* bv    = (const float*)d_in[8];
    const float* wbias = (const float*)d_in[9];
    const float* Wo    = (const float*)d_in[10];
    const float* bo    = (const float*)d_in[11];
    const float* W1    = (const float*)d_in[12];
    const float* b1    = (const float*)d_in[13];
    const float* W2    = (const float*)d_in[14];
    const float* b2    = (const float*)d_in[15];
    float* out = (float*)d_out;

    f16 *x1, *x3, *qsig, *numer, *vmat, *y, *x2, *h;
    f16 *wq, *wk, *wv, *wo, *w1, *w2;
    cudaGetSymbolAddress((void**)&x1,    g_x1);
    cudaGetSymbolAddress((void**)&x3,    g_x3);
    cudaGetSymbolAddress((void**)&qsig,  g_qsig);
    cudaGetSymbolAddress((void**)&numer, g_numer);
    cudaGetSymbolAddress((void**)&vmat,  g_v);
    cudaGetSymbolAddress((void**)&y,     g_y);
    cudaGetSymbolAddress((void**)&x2,    g_x2);
    cudaGetSymbolAddress((void**)&h,     g_h);
    cudaGetSymbolAddress((void**)&wq, g_wq);
    cudaGetSymbolAddress((void**)&wk, g_wk);
    cudaGetSymbolAddress((void**)&wv, g_wv);
    cudaGetSymbolAddress((void**)&wo, g_wo);
    cudaGetSymbolAddress((void**)&w1, g_w1);
    cudaGetSymbolAddress((void**)&w2, g_w2);

    cudaFuncSetAttribute(tc_gemm_qkv,
        cudaFuncAttributeMaxDynamicSharedMemorySize, SMEM_BYTES);
    cudaFuncSetAttribute(tc_gemm<3>,
        cudaFuncAttributeMaxDynamicSharedMemorySize, SMEM_BYTES);
    cudaFuncSetAttribute(tc_gemm<4>,
        cudaFuncAttributeMaxDynamicSharedMemorySize, SMEM_BYTES);
    cudaFuncSetAttribute(tc_gemm<5>,
        cudaFuncAttributeMaxDynamicSharedMemorySize, SMEM_BYTES);

    // 0) fused weight transpose + fp16 round (one launch)
    wsplit6_kernel<<<dim3(512, 6), 256>>>(Wq, Wk, Wv, Wo, W1, W2,
        wq, wk, wv, wo, w1, w2);

    // 1) x1 = LN(x) -> f16
    ln_f32_kernel<<<MROWS, 128>>>(x, gamma, beta, x1);

    // 2) fused Q/K/V GEMM -> f16 outputs
    dim3 gQKV(3 * (HDIM / 128), MROWS / 128);
    tc_gemm_qkv<<<gQKV, 256, SMEM_BYTES>>>(x1,
        wq, wk, wv, bq, bk, bv, wbias, qsig, numer, vmat);

    // 3) fused reduce + Y
    aft_y_kernel<<<TH / 1024, 256>>>(numer, vmat, qsig, y);

    // 4) x2 = Y @ Wo + bo + x1 -> f16
    dim3 gO(DDIM / 128, MROWS / 128);
    tc_gemm<3><<<gO, 256, SMEM_BYTES>>>(y, wo, bo, x1, nullptr, x2, DDIM, HDIM);

    // 5) x3 = LN(x2) -> f16
    ln_f16_kernel<<<MROWS, 128>>>(x2, gamma, beta, x3);

    // 6) h = gelu(x3 @ W1 + b1) -> f16
    dim3 gH(HDIM / 128, MROWS / 128);
    tc_gemm<4><<<gH, 256, SMEM_BYTES>>>(x3, w1, b1, nullptr, nullptr, h, HDIM, DDIM);

    // 7) out = 2*(h @ W2 + b2) -> f32
    tc_gemm<5><<<gO, 256, SMEM_BYTES>>>(h, w2, b2, nullptr, out, nullptr, DDIM, HDIM);
}